// round 9
// baseline (speedup 1.0000x reference)
#include <cuda_runtime.h>
#include <cuda_bf16.h>

#define NB     512
#define GLO    (-6.0f)
#define BW     (12.0f / NB)
#define INVW   (NB / 12.0f)
#define MAXB   4
#define MAXPTS 8192
#define MAXPR  (MAXPTS / 2)
#define FULLM  0xFFFFFFFFu
#define STEP   4

// Static scratch. Pair p of (cl,b) lives at g_pk[cl][b][2p] = {x0,x1,y0,y1}
// and g_pk[cl][b][2p+1] = {z0,z1,w0,w1}, w = 0.5*||p||^2. x-bin sorted.
__device__ int    g_start[2][MAXB][NB + 1];
__device__ float4 g_pk[2][MAXB][2 * MAXPR];

__device__ __forceinline__ int binOf(float x) {
    int c = (int)floorf((x - GLO) * INVW);
    return min(max(c, 0), NB - 1);
}

// ---- packed f32x2 helpers ----
__device__ __forceinline__ unsigned long long pk2(float lo, float hi) {
    unsigned long long v;
    asm("mov.b64 %0, {%1, %2};" : "=l"(v) : "f"(lo), "f"(hi));
    return v;
}
__device__ __forceinline__ unsigned long long fma2(unsigned long long a,
                                                   unsigned long long b,
                                                   unsigned long long c) {
    unsigned long long d;
    asm("fma.rn.f32x2 %0, %1, %2, %3;" : "=l"(d) : "l"(a), "l"(b), "l"(c));
    return d;
}
__device__ __forceinline__ void unpk2(unsigned long long v, float& lo, float& hi) {
    asm("mov.b64 {%0, %1}, %2;" : "=f"(lo), "=f"(hi) : "l"(v));
}

// Fused setup: one block per (cloud,batch). smem hist -> smem scan -> scatter.
__global__ __launch_bounds__(1024) void k_setup(
    const float* __restrict__ p1, const float* __restrict__ p2,
    int B, int N, int M, float* __restrict__ out)
{
    const int cl = blockIdx.x / B;
    const int b  = blockIdx.x % B;
    const int n  = cl ? M : N;
    const float* __restrict__ P = cl ? (p2 + (size_t)b * M * 3)
                                     : (p1 + (size_t)b * N * 3);
    __shared__ int hist[NB];
    __shared__ int cur[NB];
    const int t = threadIdx.x;

    if (t < NB) hist[t] = 0;
    __syncthreads();

    float xs[8], ys[8], zs[8];
    int nk = 0;
    for (int idx = t; idx < n; idx += 1024) {
        float x = P[idx * 3 + 0], y = P[idx * 3 + 1], z = P[idx * 3 + 2];
        xs[nk] = x; ys[nk] = y; zs[nk] = z; nk++;
        atomicAdd(&hist[binOf(x)], 1);
    }
    __syncthreads();

    int c = (t < NB) ? hist[t] : 0;
    for (int off = 1; off < NB; off <<= 1) {
        int v = (t < NB && t >= off) ? hist[t - off] : 0;
        __syncthreads();
        if (t < NB) hist[t] += v;
        __syncthreads();
    }
    if (t < NB) {
        int excl = hist[t] - c;
        g_start[cl][b][t] = excl;
        cur[t] = excl;
    }
    if (t == 0) {
        g_start[cl][b][NB] = n;
        if (n & 1) {  // pad the unwritten odd half so it can never win a min
            g_pk[cl][b][2 * (n >> 1) + 1].w = __int_as_float(0x7F800000);
        }
        if (blockIdx.x == 0) out[0] = 0.0f;
    }
    __syncthreads();

    nk = 0;
    for (int idx = t; idx < n; idx += 1024) {
        float x = xs[nk], y = ys[nk], z = zs[nk]; nk++;
        int pos = atomicAdd(&cur[binOf(x)], 1);
        int pr = pos >> 1, h = pos & 1;
        float* Ap = (float*)&g_pk[cl][b][2 * pr];
        float* Bp = (float*)&g_pk[cl][b][2 * pr + 1];
        Ap[h] = x;  Ap[2 + h] = y;
        Bp[h] = z;  Bp[2 + h] = 0.5f * (x * x + y * y + z * z);
    }
}

// Bidirectional stream NN: scan warp home bins, then stream outward in
// 4-bin chunks, re-testing exact per-lane termination against the
// continuously-refined best distance.
__global__ __launch_bounds__(256) void k_query(int B, int N, int M,
                                               float invBN, float invBM,
                                               float* __restrict__ out)
{
    const int dir = blockIdx.z;           // 0: p1->p2, 1: p2->p1
    const int b   = blockIdx.y;
    const int nq  = dir ? M : N;
    const int qi  = blockIdx.x * blockDim.x + threadIdx.x;
    const int qic = min(qi, nq - 1);
    const float INFv = __int_as_float(0x7F800000);

    const int qc = dir, rc = 1 - dir;

    float4 qa = g_pk[qc][b][2 * (qic >> 1)];
    float4 qb = g_pk[qc][b][2 * (qic >> 1) + 1];
    const int h = qic & 1;
    const float qx = h ? qa.y : qa.x;
    const float qy = h ? qa.w : qa.z;
    const float qz = h ? qb.y : qb.x;
    const float q2 = 2.0f * (h ? qb.w : qb.z);  // ||q||^2

    const int bq  = binOf(qx);
    const int wb0 = __reduce_min_sync(FULLM, bq);
    const int wb1 = __reduce_max_sync(FULLM, bq);

    const ulonglong2* __restrict__ base = (const ulonglong2*)&g_pk[rc][b][0];
    const int* __restrict__ st = g_start[rc][b];

    const unsigned long long nqx = pk2(-qx, -qx);
    const unsigned long long nqy = pk2(-qy, -qy);
    const unsigned long long nqz = pk2(-qz, -qz);
    float mnA = INFv, mnB = INFv;

    auto scanRange = [&](int s0, int s1) {   // point-index range -> pairs
        int p0 = s0 >> 1, p1 = (s1 + 1) >> 1;
        const ulonglong2* ptr = base + 2 * p0;
#pragma unroll 4
        for (int p = p0; p < p1; p++) {
            ulonglong2 av = __ldg(ptr);       // {x0,x1},{y0,y1}
            ulonglong2 cv = __ldg(ptr + 1);   // {z0,z1},{w0,w1}
            ptr += 2;
            unsigned long long s = fma2(av.x, nqx,
                                   fma2(av.y, nqy,
                                   fma2(cv.x, nqz, cv.y)));
            float lo, hi;
            unpk2(s, lo, hi);
            mnA = fminf(mnA, lo);
            mnB = fminf(mnB, hi);
        }
    };

    // Home bins of the warp.
    scanRange(__ldg(&st[wb0]), __ldg(&st[wb1 + 1]));
    int bL = wb0, bR = wb1;

    // Stream outward; per-lane exact termination against refined best.
    for (;;) {
        float best = fmaf(2.0f, fminf(mnA, mnB), q2);  // inf until a candidate
        bool doneL = (bL == 0);
        if (!doneL) { float dl = qx - (GLO + bL * BW);       doneL = (dl * dl >= best); }
        bool doneR = (bR == NB - 1);
        if (!doneR) { float dr = (GLO + (bR + 1) * BW) - qx; doneR = (dr * dr >= best); }
        if (__all_sync(FULLM, doneL && doneR)) break;
        bool needL = __any_sync(FULLM, !doneL) && (bL > 0);
        bool needR = __any_sync(FULLM, !doneR) && (bR < NB - 1);
        if (needL) {
            int nb = max(bL - STEP, 0);
            scanRange(__ldg(&st[nb]), __ldg(&st[bL]));
            bL = nb;
        }
        if (needR) {
            int nb = min(bR + STEP, NB - 1);
            scanRange(__ldg(&st[bR + 1]), __ldg(&st[nb + 1]));
            bR = nb;
        }
        if (!needL && !needR) break;  // safety (unreachable)
    }

    float dnn = fmaxf(fmaf(2.0f, fminf(mnA, mnB), q2), 0.0f);
    float contrib = (qi < nq) ? dnn * (dir ? invBM : invBN) : 0.0f;

    // Warp sum -> one atomic per warp.
#pragma unroll
    for (int o = 16; o > 0; o >>= 1)
        contrib += __shfl_xor_sync(FULLM, contrib, o);
    if ((threadIdx.x & 31) == 0) atomicAdd(out, contrib);
}

extern "C" void kernel_launch(void* const* d_in, const int* in_sizes, int n_in,
                              void* d_out, int out_size)
{
    const float* p1 = (const float*)d_in[0];
    const float* p2 = (const float*)d_in[1];

    const int B = 4;
    const int N = in_sizes[0] / (B * 3);
    const int M = in_sizes[1] / (B * 3);

    k_setup<<<2 * B, 1024>>>(p1, p2, B, N, M, (float*)d_out);

    const int maxNM = N > M ? N : M;
    dim3 qgrid((maxNM + 255) / 256, B, 2);
    k_query<<<qgrid, 256>>>(B, N, M,
                            1.0f / (float)(B * N), 1.0f / (float)(B * M),
                            (float*)d_out);
}